// round 6
// baseline (speedup 1.0000x reference)
#include <cuda_runtime.h>

#define BB 16
#define CIN 256
#define FF 76
#define NPIX (FF*FF)          /* 5776 */
#define NA 3
#define NCH 85
#define KK 50
#define PXB 128               /* pixels per block */
#define TPB 128
#define NPAIR (PXB/2)         /* 64 pixel-pairs per block */
#define NBLK ((NPIX + PXB - 1)/PXB)   /* 46 */
#define TOTB (NBLK*BB)                /* 736 */

typedef unsigned long long ull;

__device__ double       g_acc[5];   /* xy, wh, obj, cls, l2 */
__device__ unsigned int g_done;     /* auto-wrapping block ticket */

__constant__ float c_AW[9] = {1.25f,2.0f,4.125f,3.75f,7.75f,7.375f,14.5f,19.5f,46.625f};
__constant__ float c_AH[9] = {1.625f,3.75f,2.875f,7.625f,5.625f,14.875f,11.25f,24.75f,40.75f};
__constant__ float c_MW[3] = {1.25f,2.0f,4.125f};
__constant__ float c_MH[3] = {1.625f,3.75f,2.875f};

__device__ __forceinline__ float sigf(float x){ return 1.0f/(1.0f + expf(-x)); }

__device__ __forceinline__ float bce1(float p, float t){
    float pc = fminf(fmaxf(p, 1e-12f), 0.99999988f);
    return -(t*logf(pc) + (1.0f - t)*logf(1.0f - pc));
}

__device__ __forceinline__ void fma2(ull& acc, ull a, ull b){
    asm("fma.rn.f32x2 %0, %1, %2, %0;" : "+l"(acc) : "l"(a), "l"(b));
}
__device__ __forceinline__ float2 u2f2(ull v){
    float2 r; asm("mov.b64 {%0, %1}, %2;" : "=f"(r.x), "=f"(r.y) : "l"(v)); return r;
}

__global__ void __launch_bounds__(TPB, 5)
k_main(const float* __restrict__ xin, const float* __restrict__ labels,
       const float* __restrict__ cw,  const float* __restrict__ cb,
       float* __restrict__ dout)
{
    __shared__ ull    sW2[15][CIN];      /* (w,w) pairs: 30.7 KB */
    __shared__ union {
        ull   part[15][NPAIR];           /* half-1 conv partials  (phase A) */
        float out5[NA][PXB][5];          /* staged ch0-4 values   (phase B) */
    } sU;                                /* 7.7 KB, phases separated by bar */
    __shared__ float  sB[15];
    __shared__ float  sTx[KK], sTy[KK], sTw[KK], sTh[KK];
    __shared__ float  sX1[KK], sY1[KK], sX2[KK], sY2[KK], sAr[KK];
    __shared__ int    sCls[KK];
    __shared__ int    sOwn[NA*PXB];
    __shared__ int    sPos[KK];          /* packed (cell<<7)|cls */
    __shared__ int    sCnt;
    __shared__ float  sX[CIN];
    __shared__ double red[5][4];

    int tid = threadIdx.x;
    int b   = blockIdx.y;
    int n0  = blockIdx.x*PXB;
    int npb = NPIX - n0; if (npb > PXB) npb = PXB;   /* 128 or 16, even */

    for (int i = tid; i < NA*PXB; i += TPB) sOwn[i] = -1;
    if (tid == 0) sCnt = 0;

    /* weights as (w,w) pairs */
    for (int i = tid; i < 15*CIN; i += TPB){
        int j = i >> 8, c = i & 255;
        int a = j/5, ch = j%5;
        float w = cw[(a*NCH + ch)*CIN + c];
        float2 p = make_float2(w, w);
        sW2[j][c] = *reinterpret_cast<ull*>(&p);
    }
    if (tid < 15){ int a = tid/5, ch = tid%5; sB[tid] = cb[a*NCH + ch]; }
    if (tid >= 64 && tid < 64 + KK){
        int t = tid - 64;
        const float* L = labels + (b*KK + t)*5;
        float cls=L[0], xc=L[1], yc=L[2], w=L[3], h=L[4];
        bool valid = (cls + xc + yc + w + h) > 0.0f;
        float tx = xc*(float)FF, ty = yc*(float)FF;
        float tw = w *(float)FF, th = h *(float)FF;
        sTx[t]=tx; sTy[t]=ty; sTw[t]=tw; sTh[t]=th;
        sCls[t] = (int)cls;
        if (valid){
            sX1[t]=tx-tw*0.5f; sY1[t]=ty-th*0.5f;
            sX2[t]=tx+tw*0.5f; sY2[t]=ty+th*0.5f;
            sAr[t]=tw*th;
        } else {
            sX1[t]= 3.0e38f; sY1[t]= 3.0e38f;
            sX2[t]=-3.0e38f; sY2[t]=-3.0e38f;
            sAr[t]= 0.0f;
        }
        float ta = tw*th;
        float best = -1.0f; int bn = 0;
        #pragma unroll
        for (int a = 0; a < 9; a++){
            float inter = fminf(tw, c_AW[a]) * fminf(th, c_AH[a]);
            float iou = inter / (ta + c_AW[a]*c_AH[a] - inter);
            if (iou > best){ best = iou; bn = a; }
        }
        if (valid && bn < 3){
            int ii = (int)tx, jj = (int)ty;
            int slot = jj*FF + ii - n0;
            if (slot >= 0 && slot < PXB) atomicMax(&sOwn[bn*PXB + slot], t);
        }
    }
    __syncthreads();

    int pt   = tid & (NPAIR-1);     /* pair index within block */
    int half = tid >> 6;            /* channel half */
    int nbase = n0 + 2*pt;
    bool pv = (2*pt < npb);
    int nb = pv ? nbase : n0;
    double l_xy=0.0, l_wh=0.0, l_obj=0.0, l_cl=0.0, l_l2=0.0;

    /* ---- 15-ch conv, pixel-paired f32x2, channels split across 2 threads ---- */
    ull acc[15];
    #pragma unroll
    for (int j = 0; j < 15; j++) acc[j] = 0ULL;
    {
        const ull* xq = reinterpret_cast<const ull*>(xin + (size_t)b*CIN*NPIX + nb);
        const int ST = NPIX/2;
        const int c0 = half*128;
        ull xa0=xq[(size_t)(c0+0)*ST], xa1=xq[(size_t)(c0+1)*ST];
        ull xa2=xq[(size_t)(c0+2)*ST], xa3=xq[(size_t)(c0+3)*ST];
        ull xb0=xq[(size_t)(c0+4)*ST], xb1=xq[(size_t)(c0+5)*ST];
        ull xb2=xq[(size_t)(c0+6)*ST], xb3=xq[(size_t)(c0+7)*ST];
        #pragma unroll 2
        for (int c = 0; c < 128; c += 8){
            int cp = (c + 8 < 128) ? c0 + c + 8 : c0;
            ull y0=xq[(size_t)(cp+0)*ST], y1=xq[(size_t)(cp+1)*ST];
            ull y2=xq[(size_t)(cp+2)*ST], y3=xq[(size_t)(cp+3)*ST];
            #pragma unroll
            for (int j = 0; j < 15; j++){
                ulonglong2 wA = *reinterpret_cast<const ulonglong2*>(&sW2[j][c0+c]);
                ulonglong2 wB = *reinterpret_cast<const ulonglong2*>(&sW2[j][c0+c+2]);
                fma2(acc[j], wA.x, xa0); fma2(acc[j], wA.y, xa1);
                fma2(acc[j], wB.x, xa2); fma2(acc[j], wB.y, xa3);
            }
            int cq = (c + 12 < 128) ? c0 + c + 12 : c0;
            ull z0=xq[(size_t)(cq+0)*ST], z1=xq[(size_t)(cq+1)*ST];
            ull z2=xq[(size_t)(cq+2)*ST], z3=xq[(size_t)(cq+3)*ST];
            #pragma unroll
            for (int j = 0; j < 15; j++){
                ulonglong2 wA = *reinterpret_cast<const ulonglong2*>(&sW2[j][c0+c+4]);
                ulonglong2 wB = *reinterpret_cast<const ulonglong2*>(&sW2[j][c0+c+6]);
                fma2(acc[j], wA.x, xb0); fma2(acc[j], wA.y, xb1);
                fma2(acc[j], wB.x, xb2); fma2(acc[j], wB.y, xb3);
            }
            xa0=y0; xa1=y1; xa2=y2; xa3=y3;
            xb0=z0; xb1=z1; xb2=z2; xb3=z3;
        }
    }
    if (half == 1){
        #pragma unroll
        for (int j = 0; j < 15; j++) sU.part[j][pt] = acc[j];
    }
    __syncthreads();

    /* per-cell outputs retained in regs (reused arrays) */
    float s0[2][3], s1v[2][3], s4v[2][3], r2v[2][3], r3v[2][3];

    if (half == 0 && pv){
        float a2[2][15];
        #pragma unroll
        for (int j = 0; j < 15; j++){
            float2 f = u2f2(acc[j]);
            float2 g = u2f2(sU.part[j][pt]);
            a2[0][j] = f.x + g.x;
            a2[1][j] = f.y + g.y;
        }

        float bx1[2][3], by1[2][3], bx2[2][3], by2[2][3], bap[2][3];
        #pragma unroll
        for (int p = 0; p < 2; p++){
            int n = nbase + p;
            int h = n / FF, w = n % FF;
            #pragma unroll
            for (int a = 0; a < NA; a++){
                float r0 = a2[p][a*5+0] + sB[a*5+0];
                float r1 = a2[p][a*5+1] + sB[a*5+1];
                float r2 = a2[p][a*5+2] + sB[a*5+2];
                float r3 = a2[p][a*5+3] + sB[a*5+3];
                float r4 = a2[p][a*5+4] + sB[a*5+4];
                s0[p][a]=sigf(r0); s1v[p][a]=sigf(r1); s4v[p][a]=sigf(r4);
                r2v[p][a]=r2; r3v[p][a]=r3;
                float px = s0[p][a] + (float)w, py = s1v[p][a] + (float)h;
                float pw = expf(r2)*c_MW[a], ph = expf(r3)*c_MH[a];
                bx1[p][a]=px-pw*0.5f; by1[p][a]=py-ph*0.5f;
                bx2[p][a]=px+pw*0.5f; by2[p][a]=py+ph*0.5f;
                bap[p][a]=pw*ph;
            }
        }

        bool ig[2][3] = {{false,false,false},{false,false,false}};
        #pragma unroll 2
        for (int k = 0; k < KK; k++){
            float lx1=sX1[k], ly1=sY1[k], lx2=sX2[k], ly2=sY2[k], ar=sAr[k];
            #pragma unroll
            for (int p = 0; p < 2; p++)
            #pragma unroll
            for (int a = 0; a < NA; a++){
                float dx = fminf(bx2[p][a], lx2) - fmaxf(bx1[p][a], lx1);
                float dy = fminf(by2[p][a], ly2) - fmaxf(by1[p][a], ly1);
                float inter = dx*dy;
                bool en = (dx > 0.0f) & (dy > 0.0f);
                ig[p][a] = ig[p][a] | (en & (inter > 0.7f*(bap[p][a] + ar - inter)));
            }
        }

        #pragma unroll
        for (int p = 0; p < 2; p++){
            int n = nbase + p;
            #pragma unroll
            for (int a = 0; a < NA; a++){
                int cell = (b*NA + a)*NPIX + n;
                int k = sOwn[a*PXB + (n - n0)];
                bool m = (k >= 0);
                float obj = m ? 1.0f : (ig[p][a] ? 0.0f : 1.0f);
                float o4 = s4v[p][a] * obj;

                if (m){
                    float tx = sTx[k], ty = sTy[k], tw = sTw[k], th = sTh[k];
                    int ii = (int)tx, jj = (int)ty;
                    float tfx = tx - (float)ii, tfy = ty - (float)jj;
                    float lw = logf(tw / c_MW[a] + 1e-16f);
                    float lh = logf(th / c_MH[a] + 1e-16f);
                    float sc  = sqrtf(2.0f - tw*th/(float)NPIX);
                    float sc2 = sc*sc;
                    l_xy += (double)((bce1(s0[p][a], tfx) + bce1(s1v[p][a], tfy)) * sc2);
                    float ow2 = r2v[p][a]*sc, ow3 = r3v[p][a]*sc;
                    float tw2 = lw*sc, tw3 = lh*sc;
                    float d2 = ow2 - tw2, d3 = ow3 - tw3;
                    l_wh += 0.5*(double)(d2*d2 + d3*d3);
                    l_obj += (double)bce1(o4, 1.0f);
                    float e0 = s0[p][a] - tfx, e1 = s1v[p][a] - tfy, e4 = o4 - 1.0f;
                    l_l2 += (double)(e0*e0 + e1*e1 + d2*d2 + d3*d3 + e4*e4);
                    int idx = atomicAdd(&sCnt, 1);
                    sPos[idx] = (cell << 7) | sCls[k];
                    /* stage values: ch0..3 = s0,s1,ow2,ow3 ; ch4 = o4 */
                    r2v[p][a] = ow2; r3v[p][a] = ow3; s4v[p][a] = o4;
                } else {
                    l_obj += (double)bce1(o4, 0.0f);
                    l_l2  += (double)(o4*o4);
                    s0[p][a]=0.0f; s1v[p][a]=0.0f;
                    r2v[p][a]=0.0f; r3v[p][a]=0.0f; s4v[p][a]=o4;
                }
            }
        }
    }
    __syncthreads();   /* all sU.part reads done -> union repurpose is safe */

    if (half == 0 && pv){
        #pragma unroll
        for (int p = 0; p < 2; p++){
            int slot = nbase + p - n0;
            #pragma unroll
            for (int a = 0; a < NA; a++){
                float* o5 = &sU.out5[a][slot][0];
                o5[0]=s0[p][a]; o5[1]=s1v[p][a]; o5[2]=r2v[p][a];
                o5[3]=r3v[p][a]; o5[4]=s4v[p][a];
            }
        }
    }
    __syncthreads();

    /* ---- single-pass coalesced store of the 3 output regions ---- */
    #pragma unroll
    for (int a = 0; a < NA; a++){
        size_t e0 = 6 + ((size_t)((b*NA + a)*NPIX + n0))*NCH;
        float* base = dout + e0;
        int cnt = npb*NCH;
        int pad = (int)((4 - (e0 & 3)) & 3);
        if (pad > cnt) pad = cnt;
        if (tid < pad){
            int cell = tid/NCH, c = tid - cell*NCH;
            base[tid] = (c < 5) ? sU.out5[a][cell][c] : 0.0f;
        }
        int nv = (cnt - pad) >> 2;
        float4* b4 = (float4*)(base + pad);
        for (int j = tid; j < nv; j += TPB){
            int g = pad + (j << 2);
            float4 vv;
            {
                int cell = g/NCH, c = g - cell*NCH;
                vv.x = (c < 5) ? sU.out5[a][cell][c] : 0.0f;
            }
            {
                int cell = (g+1)/NCH, c = (g+1) - cell*NCH;
                vv.y = (c < 5) ? sU.out5[a][cell][c] : 0.0f;
            }
            {
                int cell = (g+2)/NCH, c = (g+2) - cell*NCH;
                vv.z = (c < 5) ? sU.out5[a][cell][c] : 0.0f;
            }
            {
                int cell = (g+3)/NCH, c = (g+3) - cell*NCH;
                vv.w = (c < 5) ? sU.out5[a][cell][c] : 0.0f;
            }
            b4[j] = vv;
        }
        int rem0 = pad + (nv << 2);
        if (rem0 + tid < cnt){
            int g = rem0 + tid;
            int cell = g/NCH, c = g - cell*NCH;
            base[g] = (c < 5) ? sU.out5[a][cell][c] : 0.0f;
        }
    }
    __syncthreads();   /* region store done before class-pass scatter into it */

    /* ---- class pass for positives owned by this block ---- */
    {
        int lane = tid & 31, wid = tid >> 5;
        int cnt = sCnt;
        for (int q = 0; q < cnt; q++){
            int pk   = sPos[q];
            int cell = pk >> 7;
            int cls  = pk & 127;
            int a    = (cell / NPIX) % NA;
            int pix  = cell % NPIX;
            sX[tid]       = xin[((size_t)b*CIN + tid)*NPIX + pix];
            sX[tid + 128] = xin[((size_t)b*CIN + tid + 128)*NPIX + pix];
            __syncthreads();

            const float* wbase = cw + (size_t)(a*NCH + 5 + wid*20)*CIN;
            float s[20];
            #pragma unroll
            for (int i = 0; i < 20; i++) s[i] = 0.0f;
            #pragma unroll
            for (int j = 0; j < 8; j++){
                float x = sX[lane + 32*j];
                #pragma unroll
                for (int i = 0; i < 20; i++)
                    s[i] += wbase[(size_t)i*CIN + lane + 32*j] * x;
            }
            #pragma unroll
            for (int i = 0; i < 20; i++){
                #pragma unroll
                for (int off = 16; off; off >>= 1)
                    s[i] += __shfl_down_sync(0xffffffffu, s[i], off);
            }
            if (lane == 0){
                float* oc = dout + 6 + (size_t)cell*NCH;
                #pragma unroll
                for (int i = 0; i < 20; i++){
                    int c = wid*20 + i;
                    float raw = s[i] + cb[a*NCH + 5 + c];
                    float sg = sigf(raw);
                    float t = (c == cls) ? 1.0f : 0.0f;
                    l_cl += (double)bce1(sg, t);
                    float d = sg - t;
                    l_l2 += (double)(d*d);
                    oc[5 + c] = sg;
                }
            }
            __syncthreads();
        }
    }

    /* ---- block reduce 5 doubles -> atomicAdd ---- */
    int lane = tid & 31, wid = tid >> 5;
    #pragma unroll
    for (int off = 16; off; off >>= 1){
        l_xy  += __shfl_down_sync(0xffffffffu, l_xy,  off);
        l_wh  += __shfl_down_sync(0xffffffffu, l_wh,  off);
        l_obj += __shfl_down_sync(0xffffffffu, l_obj, off);
        l_cl  += __shfl_down_sync(0xffffffffu, l_cl,  off);
        l_l2  += __shfl_down_sync(0xffffffffu, l_l2,  off);
    }
    if (lane == 0){ red[0][wid]=l_xy; red[1][wid]=l_wh; red[2][wid]=l_obj; red[3][wid]=l_cl; red[4][wid]=l_l2; }
    __syncthreads();
    if (tid == 0){
        double a0=0,a1=0,a2=0,a3=0,a4=0;
        #pragma unroll
        for (int i = 0; i < 4; i++){ a0+=red[0][i]; a1+=red[1][i]; a2+=red[2][i]; a3+=red[3][i]; a4+=red[4][i]; }
        atomicAdd(&g_acc[0], a0);
        atomicAdd(&g_acc[1], a1);
        atomicAdd(&g_acc[2], a2);
        atomicAdd(&g_acc[3], a3);
        atomicAdd(&g_acc[4], a4);

        __threadfence();
        unsigned int t = atomicInc(&g_done, TOTB - 1);
        if (t == TOTB - 1){
            double xy = atomicAdd(&g_acc[0], 0.0);
            double wh = atomicAdd(&g_acc[1], 0.0);
            double ob = atomicAdd(&g_acc[2], 0.0);
            double cl = atomicAdd(&g_acc[3], 0.0);
            double l2 = atomicAdd(&g_acc[4], 0.0);
            dout[0] = (float)(xy + wh + ob + cl);
            dout[1] = (float)xy;
            dout[2] = (float)wh;
            dout[3] = (float)ob;
            dout[4] = (float)cl;
            dout[5] = (float)l2;
            g_acc[0]=0.0; g_acc[1]=0.0; g_acc[2]=0.0; g_acc[3]=0.0; g_acc[4]=0.0;
            __threadfence();
        }
    }
}

extern "C" void kernel_launch(void* const* d_in, const int* in_sizes, int n_in,
                              void* d_out, int out_size)
{
    const float* xin    = (const float*)d_in[0];
    const float* labels = (const float*)d_in[1];
    const float* cw     = (const float*)d_in[2];
    const float* cb     = (const float*)d_in[3];
    float* dout = (float*)d_out;

    dim3 g(NBLK, BB);   /* 46 x 16 = 736 blocks */
    k_main<<<g, TPB>>>(xin, labels, cw, cb, dout);
}